// round 11
// baseline (speedup 1.0000x reference)
#include <cuda_runtime.h>
#include <cuda_fp16.h>
#include <cstdint>

#define N_TOK 65536
#define DIM   128
#define HID   256
#define NEXP  16
#define NBLK  (N_TOK / 128)
#define MAXTILES 1040
#define MLP_GRID 148

// ---------------- device scratch ----------------
__device__ int g_perm_e[NEXP][N_TOK];        // per-expert token lists (4 MB)
__device__ int g_counts[NEXP];               // running bases (zeroed by last block each run)
__device__ int g_done;
__device__ int g_ecnt[NEXP];                 // final per-expert counts snapshot
__device__ int g_ntiles;
__device__ int g_tile_e[MAXTILES];
__device__ int g_tile_ls[MAXTILES];          // local start within expert list
// packed fp16 weights: [e][chunk16][t(0..3)][n(0..255)][w(0..1)]
__device__ uint32_t g_W1p[NEXP * 8 * 4 * 512];
__device__ uint32_t g_W2p[NEXP * 16 * 4 * 512];

// ---------------- helpers ----------------
#define MMA_F16(acc, a, b) \
    asm volatile("mma.sync.aligned.m16n8k16.row.col.f32.f16.f16.f32 " \
        "{%0,%1,%2,%3}, {%4,%5,%6,%7}, {%8,%9}, {%0,%1,%2,%3};" \
        : "+f"((acc)[0]), "+f"((acc)[1]), "+f"((acc)[2]), "+f"((acc)[3]) \
        : "r"((a)[0]), "r"((a)[1]), "r"((a)[2]), "r"((a)[3]), \
          "r"((b)[0]), "r"((b)[1]))

#define CP_ASYNC16(dst, src) \
    asm volatile("cp.async.cg.shared.global [%0], [%1], 16;" :: "r"(dst), "l"(src))
#define CP_COMMIT() asm volatile("cp.async.commit_group;" ::: "memory")
#define CP_WAIT(n)  asm volatile("cp.async.wait_group %0;" :: "n"(n) : "memory")

__device__ __forceinline__ uint32_t smem_u32(const void* p) {
    uint32_t a;
    asm("{ .reg .u64 t; cvta.to.shared.u64 t, %1; cvt.u32.u64 %0, t; }" : "=r"(a) : "l"(p));
    return a;
}
__device__ __forceinline__ uint32_t pack_h2(float lo, float hi) {
    __half2 h = __floats2half2_rn(lo, hi);
    return *(uint32_t*)&h;
}

// ---------------- fused prep: pack weights + gate + scatter + tile table ----------------
#define GX_STR 132
__global__ __launch_bounds__(256) void prep_kernel(const float* __restrict__ x,
                                                   const float* __restrict__ Wg,
                                                   const float* __restrict__ bg,
                                                   const float* __restrict__ W1,
                                                   const float* __restrict__ W2) {
    extern __shared__ float sm[];
    float* xs  = sm;                         // 128 x 132
    float* wgT = xs + 128 * GX_STR;          // 16 x 132
    float* bgs = wgT + 16 * GX_STR;          // 16
    __shared__ int hist[NEXP];
    __shared__ int sh_base[NEXP];
    __shared__ int tile_pre[NEXP];
    __shared__ int is_last;

    int tid = threadIdx.x;
    int blk = blockIdx.x;
    if (tid < NEXP) { hist[tid] = 0; bgs[tid] = bg[tid]; }
    for (int i = tid; i < DIM * NEXP; i += 256) {
        int k = i >> 4, e2 = i & 15;
        wgT[e2 * GX_STR + k] = Wg[i];
    }

    long base = (long)blk * 128 * DIM;
    const float4* xg = (const float4*)(x + base);
    for (int i4 = tid; i4 < 128 * DIM / 4; i4 += 256) {
        float4 v = xg[i4];
        int row = i4 >> 5;
        int c4  = i4 & 31;
        *(float4*)(xs + row * GX_STR + c4 * 4) = v;
    }

    // ---- pack slice: this block packs 1024 W2 words + 512 W1 words ----
#pragma unroll
    for (int j = 0; j < 4; j++) {
        int i = blk * 1024 + j * 256 + tid;
        int e = i >> 15, r = i & 32767;
        int c = r >> 11, rr = r & 2047;
        int t = rr >> 9, q = rr & 511;
        int n = q >> 1,  w = q & 1;
        int k = c * 16 + 2 * t + 8 * w;
        const float* s = W2 + ((long)e * HID + k) * HID + n;
        g_W2p[i] = pack_h2(s[0], s[HID]);
    }
#pragma unroll
    for (int j = 0; j < 2; j++) {
        int i = blk * 512 + j * 256 + tid;
        int e = i >> 14, r = i & 16383;
        int c = r >> 11, rr = r & 2047;
        int t = rr >> 9, q = rr & 511;
        int n = q >> 1,  w = q & 1;
        int k = c * 16 + 2 * t + 8 * w;
        const float* s = W1 + ((long)e * DIM + k) * HID + n;
        g_W1p[i] = pack_h2(s[0], s[HID]);
    }

    __syncthreads();

    int tcol = tid & 15;
    int trow = tid >> 4;

    float acc[8];
#pragma unroll
    for (int r = 0; r < 8; r++) acc[r] = bgs[tcol];
#pragma unroll 4
    for (int k = 0; k < DIM; k += 4) {
        float4 wv = *(const float4*)(wgT + tcol * GX_STR + k);
#pragma unroll
        for (int r = 0; r < 8; r++) {
            float4 xv = *(const float4*)(xs + (trow * 8 + r) * GX_STR + k);
            acc[r] = fmaf(xv.x, wv.x, acc[r]);
            acc[r] = fmaf(xv.y, wv.y, acc[r]);
            acc[r] = fmaf(xv.z, wv.z, acc[r]);
            acc[r] = fmaf(xv.w, wv.w, acc[r]);
        }
    }

    int ei_r[8], rank_r[8];
#pragma unroll
    for (int r = 0; r < 8; r++) {
        float v = acc[r];
        int ei = tcol;
#pragma unroll
        for (int off = 8; off > 0; off >>= 1) {
            float ov = __shfl_xor_sync(0xffffffffu, v, off, 16);
            int   oe = __shfl_xor_sync(0xffffffffu, ei, off, 16);
            if (ov > v || (ov == v && oe < ei)) { v = ov; ei = oe; }
        }
        ei_r[r] = ei;
        rank_r[r] = -1;
        if (tcol == 0) rank_r[r] = atomicAdd(&hist[ei], 1);
    }
    __syncthreads();
    if (tid < NEXP) sh_base[tid] = hist[tid] ? atomicAdd(&g_counts[tid], hist[tid]) : 0;
    __syncthreads();
#pragma unroll
    for (int r = 0; r < 8; r++) {
        if (tcol == 0) {
            int token = blk * 128 + trow * 8 + r;
            g_perm_e[ei_r[r]][sh_base[ei_r[r]] + rank_r[r]] = token;
        }
    }
    __threadfence();
    __syncthreads();
    if (tid == 0) {
        int d = atomicAdd(&g_done, 1);
        is_last = (d == NBLK - 1);
    }
    __syncthreads();
    if (is_last) {
        if (tid == 0) {
            int trun = 0;
#pragma unroll
            for (int e = 0; e < NEXP; e++) {
                int c = g_counts[e];
                g_ecnt[e]   = c;
                tile_pre[e] = trun;
                trun += (c + 63) >> 6;
                g_counts[e] = 0;
            }
            g_ntiles = trun;
            g_done = 0;
        }
        __syncthreads();
        if (tid < NEXP) {
            int e = tid;
            int cnt = g_ecnt[e];
            int nt = (cnt + 63) >> 6, tp = tile_pre[e];
            for (int i = 0; i < nt; i++) {
                g_tile_e[tp + i]  = e;
                g_tile_ls[tp + i] = 64 * i;
            }
        }
        __threadfence();
    }
}

// ---------------- fp16 mma.sync grouped MLP: 1 CTA/SM, fragment-pipelined ----------------
// 8 warps as 2(M) x 4(N); warp tile 32x64 (fm=2, fn=8); 12 chunks of k=32; 4 smem stages.
// Each warp holds cur+next fragment register sets; loads for step s+1 issue
// before the MMAs of step s, so the MMA stream is near-continuous per warp.
#define XS_STRW 68
#define H1_STRW 132
#define NCH 12
#define WROW 520
#define WS_STAGE (8 * WROW)
#define F_WS    0
#define F_B1S   (4 * WS_STAGE)
#define F_B2S   (F_B1S + 256)
#define F_W3S   (F_B2S + 256)
#define F_PS    (F_W3S + 256)
#define F_UNION (F_PS + 256)
#define MLP_SMEM ((F_UNION + 64 * H1_STRW) * 4)

__device__ __forceinline__ void cp_slice(const uint32_t* __restrict__ chunk_base,
                                         uint32_t ws_stage_smem, int wm, int wn, int lane) {
#pragma unroll
    for (int i = 0; i < 4; i++) {
        int row = wm * 4 + i;
        uint32_t off = (uint32_t)(row * WROW + wn * 128 + lane * 4) * 4u;
        CP_ASYNC16(ws_stage_smem + off, chunk_base + (long)row * 512 + wn * 128 + lane * 4);
    }
}

template<int STRW>
__device__ __forceinline__ void load_a(uint32_t a[2][4], const uint32_t* p) {
    a[0][0] = p[0];
    a[0][1] = p[8 * STRW];
    a[0][2] = p[4];
    a[0][3] = p[8 * STRW + 4];
    a[1][0] = p[16 * STRW];
    a[1][1] = p[24 * STRW];
    a[1][2] = p[16 * STRW + 4];
    a[1][3] = p[24 * STRW + 4];
}

__device__ __forceinline__ void load_b(uint32_t b[8][2], const uint32_t* stg,
                                       int kk, int t, int bcol) {
    const uint2* wr = (const uint2*)(stg + (kk * 4 + t) * WROW + bcol);
#pragma unroll
    for (int fn = 0; fn < 8; fn++) {
        uint2 v = wr[fn * 8];
        b[fn][0] = v.x;
        b[fn][1] = v.y;
    }
}

__device__ __forceinline__ void mma_all(float acc[2][8][4],
                                        const uint32_t a[2][4], const uint32_t b[8][2]) {
#pragma unroll
    for (int fm = 0; fm < 2; fm++)
#pragma unroll
        for (int fn = 0; fn < 8; fn++)
            MMA_F16(acc[fm][fn], a[fm], b[fn]);
}

__global__ __launch_bounds__(256, 1) void mlp_tc_kernel(
        const float* __restrict__ x,
        const float* __restrict__ b1, const float* __restrict__ b2,
        const float* __restrict__ W3, const float* __restrict__ b3,
        float* __restrict__ out) {
    extern __shared__ float sm[];
    float* b1s = sm + F_B1S;
    float* b2s = sm + F_B2S;
    float* w3s = sm + F_W3S;
    float* ps  = sm + F_PS;
    uint32_t* un = (uint32_t*)(sm + F_UNION);
    uint32_t ws0 = smem_u32(sm + F_WS);
    const uint32_t* wsw = (const uint32_t*)(sm + F_WS);

    int tid = threadIdx.x;
    int wid = tid >> 5, lid = tid & 31;
    int g = lid >> 2, t = lid & 3;
    int wm = wid & 1;
    int wn = wid >> 1;
    int bcol = (wn * 64 + g) * 2;

    const uint32_t* aX = un + (wm * 32 + g) * XS_STRW + t;   // A base, GEMM1
    const uint32_t* aH = un + (wm * 32 + g) * H1_STRW + t;   // A base, GEMM2

    int ntiles = g_ntiles;

    for (int tile = blockIdx.x; tile < ntiles; tile += MLP_GRID) {
        int e   = g_tile_e[tile];
        int ls  = g_tile_ls[tile];
        int cnt = min(64, g_ecnt[e] - ls);
        const int* perm = g_perm_e[e] + ls;

        b1s[tid] = b1[e * HID + tid];
        b2s[tid] = b2[e * HID + tid];
        w3s[tid] = W3[e * HID + tid];

        // gather A1 = x[perm] -> fp16 xs [64 rows][64 words, stride 68]
#pragma unroll
        for (int i = 0; i < 8; i++) {
            int f   = tid + 256 * i;
            int row = f >> 5;
            int c4  = f & 31;
            float4 v = make_float4(0.f, 0.f, 0.f, 0.f);
            if (row < cnt) {
                int gt = perm[row];
                v = *(const float4*)(x + (long)gt * DIM + c4 * 4);
            }
            uint32_t* dst = un + row * XS_STRW + c4 * 2;
            dst[0] = pack_h2(v.x, v.y);
            dst[1] = pack_h2(v.z, v.w);
        }

        const uint32_t* W1e = g_W1p + (long)e * 16384;
        const uint32_t* W2e = g_W2p + (long)e * 32768;

        float acc[2][8][4];
#pragma unroll
        for (int fm = 0; fm < 2; fm++)
#pragma unroll
            for (int fn = 0; fn < 8; fn++)
#pragma unroll
                for (int q = 0; q < 4; q++) acc[fm][fn][q] = 0.f;

        // prologue: each warp prefetches its slice for chunks 0,1,2
#pragma unroll
        for (int p = 0; p < 3; p++) {
            const uint32_t* src = (p < 4) ? (W1e + (long)p * 4096)
                                          : (W2e + (long)(p - 4) * 4096);
            cp_slice(src, ws0 + (uint32_t)((p & 3) * WS_STAGE) * 4u, wm, wn, lid);
            CP_COMMIT();
        }

        uint32_t Ca[2][4], Cb[8][2], Na[2][4], Nb[8][2];

#pragma unroll 1
        for (int ch = 0; ch < NCH; ch++) {
            if (ch < NCH - 1) CP_WAIT(1);     // stages <= ch+1 complete (this warp)
            else              CP_WAIT(0);
            __syncthreads();                  // publish all warps' stage writes <= ch+1
            if (ch + 3 < NCH) {
                int p = ch + 3;
                const uint32_t* src = (p < 4) ? (W1e + (long)p * 4096)
                                              : (W2e + (long)(p - 4) * 4096);
                cp_slice(src, ws0 + (uint32_t)((p & 3) * WS_STAGE) * 4u, wm, wn, lid);
                CP_COMMIT();
            }

            const uint32_t* stg  = wsw + (ch & 3) * WS_STAGE;
            const uint32_t* stgN = wsw + ((ch + 1) & 3) * WS_STAGE;

            if (ch == 4) {
                // epilogue 1: h1 = fp16(relu(acc + b1)) over the union region
                // (entry sync above ordered all xs reads of chunks 0..3)
#pragma unroll
                for (int fm = 0; fm < 2; fm++) {
                    int r = wm * 32 + fm * 16 + g;
#pragma unroll
                    for (int fn = 0; fn < 8; fn++) {
                        int c = wn * 64 + fn * 8 + t * 2;
                        un[r * H1_STRW + c / 2] =
                            pack_h2(fmaxf(acc[fm][fn][0] + b1s[c],     0.f),
                                    fmaxf(acc[fm][fn][1] + b1s[c + 1], 0.f));
                        un[(r + 8) * H1_STRW + c / 2] =
                            pack_h2(fmaxf(acc[fm][fn][2] + b1s[c],     0.f),
                                    fmaxf(acc[fm][fn][3] + b1s[c + 1], 0.f));
                        acc[fm][fn][0] = 0.f; acc[fm][fn][1] = 0.f;
                        acc[fm][fn][2] = 0.f; acc[fm][fn][3] = 0.f;
                    }
                }
                __syncthreads();              // h1 visible to all warps
            }

            // refill cur frags at pipeline breaks (tile start / GEMM boundary)
            if (ch == 0) {
                load_a<XS_STRW>(Ca, aX + 0);
                load_b(Cb, stg, 0, t, bcol);
            } else if (ch == 4) {
                load_a<H1_STRW>(Ca, aH + 0);
                load_b(Cb, stg, 0, t, bcol);
            }

            // next frags for (ch, kk=1)
            if (ch < 4) load_a<XS_STRW>(Na, aX + ch * 16 + 8);
            else        load_a<H1_STRW>(Na, aH + (ch - 4) * 16 + 8);
            load_b(Nb, stg, 1, t, bcol);

            mma_all(acc, Ca, Cb);             // (ch, kk=0)

            // prefetch cur frags for (ch+1, kk=0) -- skipped across pipeline breaks
            if (ch != 3 && ch != NCH - 1) {
                if (ch + 1 < 4) load_a<XS_STRW>(Ca, aX + (ch + 1) * 16);
                else            load_a<H1_STRW>(Ca, aH + (ch + 1 - 4) * 16);
                load_b(Cb, stgN, 0, t, bcol);
            }

            mma_all(acc, Na, Nb);             // (ch, kk=1)
        }

        // epilogue 2: y = relu(acc + b2) . w3 + b3
        float part[2][2];
#pragma unroll
        for (int fm = 0; fm < 2; fm++) { part[fm][0] = 0.f; part[fm][1] = 0.f; }
#pragma unroll
        for (int fm = 0; fm < 2; fm++)
#pragma unroll
            for (int fn = 0; fn < 8; fn++) {
                int c = wn * 64 + fn * 8 + t * 2;
                part[fm][0] = fmaf(fmaxf(acc[fm][fn][0] + b2s[c],     0.f), w3s[c],     part[fm][0]);
                part[fm][0] = fmaf(fmaxf(acc[fm][fn][1] + b2s[c + 1], 0.f), w3s[c + 1], part[fm][0]);
                part[fm][1] = fmaf(fmaxf(acc[fm][fn][2] + b2s[c],     0.f), w3s[c],     part[fm][1]);
                part[fm][1] = fmaf(fmaxf(acc[fm][fn][3] + b2s[c + 1], 0.f), w3s[c + 1], part[fm][1]);
            }
#pragma unroll
        for (int fm = 0; fm < 2; fm++)
#pragma unroll
            for (int h = 0; h < 2; h++) {
                part[fm][h] += __shfl_xor_sync(0xffffffffu, part[fm][h], 1);
                part[fm][h] += __shfl_xor_sync(0xffffffffu, part[fm][h], 2);
            }
        if (t == 0) {
#pragma unroll
            for (int fm = 0; fm < 2; fm++) {
                int r = wm * 32 + fm * 16 + g;
                ps[r * 4 + wn]       = part[fm][0];
                ps[(r + 8) * 4 + wn] = part[fm][1];
            }
        }
        __syncthreads();

        if (tid < cnt)
            out[perm[tid]] = ps[tid * 4] + ps[tid * 4 + 1]
                           + ps[tid * 4 + 2] + ps[tid * 4 + 3] + b3[e];
        __syncthreads();                // ps/un safe to reuse next tile
    }
}

// ---------------- launch ----------------
extern "C" void kernel_launch(void* const* d_in, const int* in_sizes, int n_in,
                              void* d_out, int out_size) {
    const float* x  = (const float*)d_in[0];
    const float* Wg = (const float*)d_in[1];
    const float* bg = (const float*)d_in[2];
    const float* W1 = (const float*)d_in[3];
    const float* b1 = (const float*)d_in[4];
    const float* W2 = (const float*)d_in[5];
    const float* b2 = (const float*)d_in[6];
    const float* W3 = (const float*)d_in[7];
    const float* b3 = (const float*)d_in[8];
    float* out = (float*)d_out;

    size_t prep_smem = (size_t)(128 * GX_STR + 16 * GX_STR + 16) * sizeof(float);
    cudaFuncSetAttribute(prep_kernel, cudaFuncAttributeMaxDynamicSharedMemorySize, (int)prep_smem);
    cudaFuncSetAttribute(mlp_tc_kernel, cudaFuncAttributeMaxDynamicSharedMemorySize, MLP_SMEM);

    prep_kernel<<<NBLK, 256, prep_smem>>>(x, Wg, bg, W1, W2);
    mlp_tc_kernel<<<MLP_GRID, 256, MLP_SMEM>>>(x, b1, b2, W3, b3, out);
    (void)n_in; (void)in_sizes; (void)out_size;
}

// round 12
// speedup vs baseline: 1.1914x; 1.1914x over previous
#include <cuda_runtime.h>
#include <cuda_fp16.h>
#include <cstdint>

#define N_TOK 65536
#define DIM   128
#define HID   256
#define NEXP  16
#define NBLK  (N_TOK / 128)
#define MAXTILES 1040
#define MLP_GRID 296

// ---------------- device scratch ----------------
__device__ int g_perm_e[NEXP][N_TOK];        // per-expert token lists (4 MB)
__device__ int g_counts[NEXP];               // running bases (zeroed by last block each run)
__device__ int g_done;
__device__ int g_ecnt[NEXP];                 // final per-expert counts snapshot
__device__ int g_ntiles;
__device__ int g_tile_e[MAXTILES];
__device__ int g_tile_ls[MAXTILES];          // local start within expert list
// packed fp16 weights: [e][chunk16][t(0..3)][n(0..255)][w(0..1)]
__device__ uint32_t g_W1p[NEXP * 8 * 4 * 512];
__device__ uint32_t g_W2p[NEXP * 16 * 4 * 512];

// ---------------- helpers ----------------
#define MMA_F16(acc, a, b) \
    asm volatile("mma.sync.aligned.m16n8k16.row.col.f32.f16.f16.f32 " \
        "{%0,%1,%2,%3}, {%4,%5,%6,%7}, {%8,%9}, {%0,%1,%2,%3};" \
        : "+f"((acc)[0]), "+f"((acc)[1]), "+f"((acc)[2]), "+f"((acc)[3]) \
        : "r"((a)[0]), "r"((a)[1]), "r"((a)[2]), "r"((a)[3]), \
          "r"((b)[0]), "r"((b)[1]))

#define CP_ASYNC16(dst, src) \
    asm volatile("cp.async.cg.shared.global [%0], [%1], 16;" :: "r"(dst), "l"(src))
#define CP_COMMIT() asm volatile("cp.async.commit_group;" ::: "memory")
#define CP_WAIT(n)  asm volatile("cp.async.wait_group %0;" :: "n"(n) : "memory")
#define BAR_PAIR(id) asm volatile("bar.sync %0, 64;" :: "r"(id) : "memory")

__device__ __forceinline__ uint32_t smem_u32(const void* p) {
    uint32_t a;
    asm("{ .reg .u64 t; cvta.to.shared.u64 t, %1; cvt.u32.u64 %0, t; }" : "=r"(a) : "l"(p));
    return a;
}
__device__ __forceinline__ uint32_t pack_h2(float lo, float hi) {
    __half2 h = __floats2half2_rn(lo, hi);
    return *(uint32_t*)&h;
}

// ---------------- fused prep: pack weights + gate (global-x) + scatter + tile table ----------------
#define GX_STR 132
__global__ __launch_bounds__(256) void prep_kernel(const float* __restrict__ x,
                                                   const float* __restrict__ Wg,
                                                   const float* __restrict__ bg,
                                                   const float* __restrict__ W1,
                                                   const float* __restrict__ W2) {
    extern __shared__ float sm[];
    float* wgT = sm;                         // 16 x 132 (transposed: [e][k])
    float* bgs = wgT + 16 * GX_STR;          // 16
    __shared__ int hist[NEXP];
    __shared__ int sh_base[NEXP];
    __shared__ int tile_pre[NEXP];
    __shared__ int is_last;

    int tid = threadIdx.x;
    int blk = blockIdx.x;
    if (tid < NEXP) { hist[tid] = 0; bgs[tid] = bg[tid]; }
    for (int i = tid; i < DIM * NEXP; i += 256) {
        int k = i >> 4, e2 = i & 15;
        wgT[e2 * GX_STR + k] = Wg[i];
    }

    // ---- pack slice: this block packs 1024 W2 words + 512 W1 words ----
#pragma unroll
    for (int j = 0; j < 4; j++) {
        int i = blk * 1024 + j * 256 + tid;
        int e = i >> 15, r = i & 32767;
        int c = r >> 11, rr = r & 2047;
        int t = rr >> 9, q = rr & 511;
        int n = q >> 1,  w = q & 1;
        int k = c * 16 + 2 * t + 8 * w;
        const float* s = W2 + ((long)e * HID + k) * HID + n;
        g_W2p[i] = pack_h2(s[0], s[HID]);
    }
#pragma unroll
    for (int j = 0; j < 2; j++) {
        int i = blk * 512 + j * 256 + tid;
        int e = i >> 14, r = i & 16383;
        int c = r >> 11, rr = r & 2047;
        int t = rr >> 9, q = rr & 511;
        int n = q >> 1,  w = q & 1;
        int k = c * 16 + 2 * t + 8 * w;
        const float* s = W1 + ((long)e * DIM + k) * HID + n;
        g_W1p[i] = pack_h2(s[0], s[HID]);
    }

    __syncthreads();                         // wgT/bgs ready

    int tcol = tid & 15;
    int trow = tid >> 4;

    // gate logits: x read directly from global (L1 broadcast), same fmaf order as before
    const float* xr = x + (long)(blk * 128 + trow * 8) * DIM;

    float acc[8];
#pragma unroll
    for (int r = 0; r < 8; r++) acc[r] = bgs[tcol];
#pragma unroll 4
    for (int k = 0; k < DIM; k += 4) {
        float4 wv = *(const float4*)(wgT + tcol * GX_STR + k);
#pragma unroll
        for (int r = 0; r < 8; r++) {
            float4 xv = __ldg((const float4*)(xr + (long)r * DIM + k));
            acc[r] = fmaf(xv.x, wv.x, acc[r]);
            acc[r] = fmaf(xv.y, wv.y, acc[r]);
            acc[r] = fmaf(xv.z, wv.z, acc[r]);
            acc[r] = fmaf(xv.w, wv.w, acc[r]);
        }
    }

    int ei_r[8], rank_r[8];
#pragma unroll
    for (int r = 0; r < 8; r++) {
        float v = acc[r];
        int ei = tcol;
#pragma unroll
        for (int off = 8; off > 0; off >>= 1) {
            float ov = __shfl_xor_sync(0xffffffffu, v, off, 16);
            int   oe = __shfl_xor_sync(0xffffffffu, ei, off, 16);
            if (ov > v || (ov == v && oe < ei)) { v = ov; ei = oe; }
        }
        ei_r[r] = ei;
        rank_r[r] = -1;
        if (tcol == 0) rank_r[r] = atomicAdd(&hist[ei], 1);
    }
    __syncthreads();
    if (tid < NEXP) sh_base[tid] = hist[tid] ? atomicAdd(&g_counts[tid], hist[tid]) : 0;
    __syncthreads();
#pragma unroll
    for (int r = 0; r < 8; r++) {
        if (tcol == 0) {
            int token = blk * 128 + trow * 8 + r;
            g_perm_e[ei_r[r]][sh_base[ei_r[r]] + rank_r[r]] = token;
        }
    }
    __threadfence();
    __syncthreads();
    if (tid == 0) {
        int d = atomicAdd(&g_done, 1);
        is_last = (d == NBLK - 1);
    }
    __syncthreads();
    if (is_last) {
        if (tid == 0) {
            int trun = 0;
#pragma unroll
            for (int e = 0; e < NEXP; e++) {
                int c = g_counts[e];
                g_ecnt[e]   = c;
                tile_pre[e] = trun;
                trun += (c + 63) >> 6;
                g_counts[e] = 0;
            }
            g_ntiles = trun;
            g_done = 0;
        }
        __syncthreads();
        if (tid < NEXP) {
            int e = tid;
            int cnt = g_ecnt[e];
            int nt = (cnt + 63) >> 6, tp = tile_pre[e];
            for (int i = 0; i < nt; i++) {
                g_tile_e[tp + i]  = e;
                g_tile_ls[tp + i] = 64 * i;
            }
        }
        __threadfence();
    }
}

// ---------------- fp16 mma.sync grouped MLP: persistent, pairwise barriers (R10 mlp) ----------------
#define XS_STRW 68
#define H1_STRW 132
#define NCH 12
#define WROW 520
#define WS_STAGE (8 * WROW)
#define F_WS    0
#define F_B1S   (4 * WS_STAGE)
#define F_B2S   (F_B1S + 256)
#define F_W3S   (F_B2S + 256)
#define F_PS    (F_W3S + 256)
#define F_UNION (F_PS + 256)
#define MLP_SMEM ((F_UNION + 64 * H1_STRW) * 4)

__device__ __forceinline__ void cp_slice(const uint32_t* __restrict__ chunk_base,
                                         uint32_t ws_stage_smem, int wm, int wn, int lane) {
#pragma unroll
    for (int i = 0; i < 4; i++) {
        int row = wm * 4 + i;
        uint32_t off = (uint32_t)(row * WROW + wn * 128 + lane * 4) * 4u;
        CP_ASYNC16(ws_stage_smem + off, chunk_base + (long)row * 512 + wn * 128 + lane * 4);
    }
}

__global__ __launch_bounds__(256, 2) void mlp_tc_kernel(
        const float* __restrict__ x,
        const float* __restrict__ b1, const float* __restrict__ b2,
        const float* __restrict__ W3, const float* __restrict__ b3,
        float* __restrict__ out) {
    extern __shared__ float sm[];
    float* b1s = sm + F_B1S;
    float* b2s = sm + F_B2S;
    float* w3s = sm + F_W3S;
    float* ps  = sm + F_PS;
    uint32_t* un = (uint32_t*)(sm + F_UNION);
    uint32_t ws0 = smem_u32(sm + F_WS);
    const uint32_t* wsw = (const uint32_t*)(sm + F_WS);

    int tid = threadIdx.x;
    int wid = tid >> 5, lid = tid & 31;
    int g = lid >> 2, t = lid & 3;
    int wm = wid & 1;
    int wn = wid >> 1;
    int bar_id = 1 + wn;

    int ntiles = g_ntiles;

    for (int tile = blockIdx.x; tile < ntiles; tile += MLP_GRID) {
        int e   = g_tile_e[tile];
        int ls  = g_tile_ls[tile];
        int cnt = min(64, g_ecnt[e] - ls);
        const int* perm = g_perm_e[e] + ls;

        b1s[tid] = b1[e * HID + tid];
        b2s[tid] = b2[e * HID + tid];
        w3s[tid] = W3[e * HID + tid];

        // gather A1 = x[perm] -> fp16 xs [64 rows][64 words, stride 68]
#pragma unroll
        for (int i = 0; i < 8; i++) {
            int f   = tid + 256 * i;
            int row = f >> 5;
            int c4  = f & 31;
            float4 v = make_float4(0.f, 0.f, 0.f, 0.f);
            if (row < cnt) {
                int gt = perm[row];
                v = *(const float4*)(x + (long)gt * DIM + c4 * 4);
            }
            uint32_t* dst = un + row * XS_STRW + c4 * 2;
            dst[0] = pack_h2(v.x, v.y);
            dst[1] = pack_h2(v.z, v.w);
        }

        const uint32_t* W1e = g_W1p + (long)e * 16384;
        const uint32_t* W2e = g_W2p + (long)e * 32768;

        float acc[2][8][4];
#pragma unroll
        for (int fm = 0; fm < 2; fm++)
#pragma unroll
            for (int fn = 0; fn < 8; fn++)
#pragma unroll
                for (int q = 0; q < 4; q++) acc[fm][fn][q] = 0.f;

        // prologue: each warp prefetches its slice for chunks 0,1,2
#pragma unroll
        for (int p = 0; p < 3; p++) {
            const uint32_t* src = (p < 4) ? (W1e + (long)p * 4096)
                                          : (W2e + (long)(p - 4) * 4096);
            cp_slice(src, ws0 + (uint32_t)((p & 3) * WS_STAGE) * 4u, wm, wn, lid);
            CP_COMMIT();
        }
        __syncthreads();                // xs + biases visible

#pragma unroll 1
        for (int ch = 0; ch < NCH; ch++) {
            if (ch < NCH - 2)       CP_WAIT(2);
            else if (ch == NCH - 2) CP_WAIT(1);
            else                    CP_WAIT(0);
            BAR_PAIR(bar_id);
            if (ch + 3 < NCH) {
                int p = ch + 3;
                const uint32_t* src = (p < 4) ? (W1e + (long)p * 4096)
                                              : (W2e + (long)(p - 4) * 4096);
                cp_slice(src, ws0 + (uint32_t)((p & 3) * WS_STAGE) * 4u, wm, wn, lid);
                CP_COMMIT();
            }

            if (ch == 4) {
                __syncthreads();        // all warps done reading xs (chunks 0..3)
                // epilogue 1: h1 = fp16(relu(acc + b1)) into union (stride 132 words)
#pragma unroll
                for (int fm = 0; fm < 2; fm++) {
                    int r = wm * 32 + fm * 16 + g;
#pragma unroll
                    for (int fn = 0; fn < 8; fn++) {
                        int c = wn * 64 + fn * 8 + t * 2;
                        un[r * H1_STRW + c / 2] =
                            pack_h2(fmaxf(acc[fm][fn][0] + b1s[c],     0.f),
                                    fmaxf(acc[fm][fn][1] + b1s[c + 1], 0.f));
                        un[(r + 8) * H1_STRW + c / 2] =
                            pack_h2(fmaxf(acc[fm][fn][2] + b1s[c],     0.f),
                                    fmaxf(acc[fm][fn][3] + b1s[c + 1], 0.f));
                        acc[fm][fn][0] = 0.f; acc[fm][fn][1] = 0.f;
                        acc[fm][fn][2] = 0.f; acc[fm][fn][3] = 0.f;
                    }
                }
                __syncthreads();        // h1 visible to all warps
            }

            const uint32_t* stg = wsw + (ch & 3) * WS_STAGE;
#pragma unroll
            for (int kk = 0; kk < 2; kk++) {
                uint32_t a[2][4];
                if (ch < 4) {
#pragma unroll
                    for (int fm = 0; fm < 2; fm++) {
                        int row = wm * 32 + fm * 16 + g;
                        const uint32_t* xr2 = un + row * XS_STRW + ch * 16 + kk * 8 + t;
                        a[fm][0] = xr2[0];
                        a[fm][1] = xr2[8 * XS_STRW];
                        a[fm][2] = xr2[4];
                        a[fm][3] = xr2[8 * XS_STRW + 4];
                    }
                } else {
#pragma unroll
                    for (int fm = 0; fm < 2; fm++) {
                        int row = wm * 32 + fm * 16 + g;
                        const uint32_t* hr = un + row * H1_STRW + (ch - 4) * 16 + kk * 8 + t;
                        a[fm][0] = hr[0];
                        a[fm][1] = hr[8 * H1_STRW];
                        a[fm][2] = hr[4];
                        a[fm][3] = hr[8 * H1_STRW + 4];
                    }
                }
                uint32_t b[8][2];
                const uint2* wr = (const uint2*)(stg + (kk * 4 + t) * WROW + (wn * 64 + g) * 2);
#pragma unroll
                for (int fn = 0; fn < 8; fn++) {
                    uint2 bv = wr[fn * 8];
                    b[fn][0] = bv.x;
                    b[fn][1] = bv.y;
                }
#pragma unroll
                for (int fm = 0; fm < 2; fm++)
#pragma unroll
                    for (int fn = 0; fn < 8; fn++)
                        MMA_F16(acc[fm][fn], a[fm], b[fn]);
            }
        }

        // epilogue 2: y = relu(acc + b2) . w3 + b3
        float part[2][2];
#pragma unroll
        for (int fm = 0; fm < 2; fm++) { part[fm][0] = 0.f; part[fm][1] = 0.f; }
#pragma unroll
        for (int fm = 0; fm < 2; fm++)
#pragma unroll
            for (int fn = 0; fn < 8; fn++) {
                int c = wn * 64 + fn * 8 + t * 2;
                part[fm][0] = fmaf(fmaxf(acc[fm][fn][0] + b2s[c],     0.f), w3s[c],     part[fm][0]);
                part[fm][0] = fmaf(fmaxf(acc[fm][fn][1] + b2s[c + 1], 0.f), w3s[c + 1], part[fm][0]);
                part[fm][1] = fmaf(fmaxf(acc[fm][fn][2] + b2s[c],     0.f), w3s[c],     part[fm][1]);
                part[fm][1] = fmaf(fmaxf(acc[fm][fn][3] + b2s[c + 1], 0.f), w3s[c + 1], part[fm][1]);
            }
#pragma unroll
        for (int fm = 0; fm < 2; fm++)
#pragma unroll
            for (int h = 0; h < 2; h++) {
                part[fm][h] += __shfl_xor_sync(0xffffffffu, part[fm][h], 1);
                part[fm][h] += __shfl_xor_sync(0xffffffffu, part[fm][h], 2);
            }
        if (t == 0) {
#pragma unroll
            for (int fm = 0; fm < 2; fm++) {
                int r = wm * 32 + fm * 16 + g;
                ps[r * 4 + wn]       = part[fm][0];
                ps[(r + 8) * 4 + wn] = part[fm][1];
            }
        }
        __syncthreads();

        if (tid < cnt)
            out[perm[tid]] = ps[tid * 4] + ps[tid * 4 + 1]
                           + ps[tid * 4 + 2] + ps[tid * 4 + 3] + b3[e];
        __syncthreads();                // ps/un safe to reuse next tile
    }
}

// ---------------- launch ----------------
extern "C" void kernel_launch(void* const* d_in, const int* in_sizes, int n_in,
                              void* d_out, int out_size) {
    const float* x  = (const float*)d_in[0];
    const float* Wg = (const float*)d_in[1];
    const float* bg = (const float*)d_in[2];
    const float* W1 = (const float*)d_in[3];
    const float* b1 = (const float*)d_in[4];
    const float* W2 = (const float*)d_in[5];
    const float* b2 = (const float*)d_in[6];
    const float* W3 = (const float*)d_in[7];
    const float* b3 = (const float*)d_in[8];
    float* out = (float*)d_out;

    size_t prep_smem = (size_t)(16 * GX_STR + 16) * sizeof(float);
    cudaFuncSetAttribute(prep_kernel, cudaFuncAttributeMaxDynamicSharedMemorySize, (int)prep_smem);
    cudaFuncSetAttribute(mlp_tc_kernel, cudaFuncAttributeMaxDynamicSharedMemorySize, MLP_SMEM);

    prep_kernel<<<NBLK, 256, prep_smem>>>(x, Wg, bg, W1, W2);
    mlp_tc_kernel<<<MLP_GRID, 256, MLP_SMEM>>>(x, b1, b2, W3, b3, out);
    (void)n_in; (void)in_sizes; (void)out_size;
}